// round 5
// baseline (speedup 1.0000x reference)
#include <cuda_runtime.h>
#include <cstdint>

// LSTM T=8192, H=128. Cluster of 4 CTAs x 128 threads (4 SMs, 1 warp/SMSP).
// CTA q owns rows {gate*128 + q*32 + m} -> h elements [q*32, q*32+32).
// All weights in registers (64 u64/thread). Gate combine via shfl.bfly.
// h exchange: each producer lane st.async's its h to all 3 peers; phase
// barrier armed with expect_tx = 96 floats = 384 B. Ping-pong mbarriers.

#define HD 128
#define TPC 128
#define QTR 32
#define TXB 384   // 3 peers * 32 floats * 4 B

typedef unsigned long long u64;

__device__ __forceinline__ u64 ffma2(u64 a, u64 b, u64 c) {
    u64 d;
    asm("fma.rn.f32x2 %0, %1, %2, %3;" : "=l"(d) : "l"(a), "l"(b), "l"(c));
    return d;
}
__device__ __forceinline__ u64 pack2(float lo, float hi) {
    u64 r;
    asm("mov.b64 %0, {%1, %2};" : "=l"(r) : "f"(lo), "f"(hi));
    return r;
}
__device__ __forceinline__ void unpack2(u64 v, float& lo, float& hi) {
    asm("mov.b64 {%0, %1}, %2;" : "=f"(lo), "=f"(hi) : "l"(v));
}
__device__ __forceinline__ float sigm(float x) {
    x = fminf(fmaxf(x, -30.f), 30.f);
    return __fdividef(1.f, 1.f + __expf(-x));
}
__device__ __forceinline__ float tanh_(float x) {
    x = fminf(fmaxf(x, -15.f), 15.f);
    float e = __expf(-2.f * x);
    return __fdividef(1.f - e, 1.f + e);
}
__device__ __forceinline__ uint32_t smem_u32(const void* p) {
    return (uint32_t)__cvta_generic_to_shared(p);
}
__device__ __forceinline__ uint32_t mapa_u32(uint32_t addr, uint32_t rank) {
    uint32_t r;
    asm("mapa.shared::cluster.u32 %0, %1, %2;" : "=r"(r) : "r"(addr), "r"(rank));
    return r;
}
__device__ __forceinline__ void mbar_init(uint32_t a, uint32_t cnt) {
    asm volatile("mbarrier.init.shared.b64 [%0], %1;" :: "r"(a), "r"(cnt) : "memory");
}
__device__ __forceinline__ void mbar_arrive(uint32_t a) {
    asm volatile("mbarrier.arrive.shared.b64 _, [%0];" :: "r"(a) : "memory");
}
__device__ __forceinline__ void mbar_arrive_expect_tx(uint32_t a, uint32_t tx) {
    asm volatile("mbarrier.arrive.expect_tx.shared.b64 _, [%0], %1;"
                 :: "r"(a), "r"(tx) : "memory");
}
__device__ __forceinline__ void st_async_f32(uint32_t raddr, float v, uint32_t rmbar) {
    asm volatile(
        "st.async.shared::cluster.mbarrier::complete_tx::bytes.f32 [%0], %1, [%2];"
        :: "r"(raddr), "f"(v), "r"(rmbar) : "memory");
}
__device__ __forceinline__ void mbar_wait(uint32_t a, uint32_t parity) {
    asm volatile(
        "{\n\t"
        ".reg .pred P;\n\t"
        "WL_%=:\n\t"
        "mbarrier.try_wait.parity.acquire.cluster.shared::cta.b64 P, [%0], %1;\n\t"
        "@P bra WD_%=;\n\t"
        "bra WL_%=;\n\t"
        "WD_%=:\n\t"
        "}" :: "r"(a), "r"(parity) : "memory");
}
__device__ __forceinline__ void cluster_sync() {
    asm volatile("barrier.cluster.arrive.aligned;" ::: "memory");
    asm volatile("barrier.cluster.wait.aligned;" ::: "memory");
}

extern "C" __global__ void __launch_bounds__(TPC, 1) __cluster_dims__(4, 1, 1)
lstm_cluster4_kernel(const float* __restrict__ x,
                     const float* __restrict__ W_ih,
                     const float* __restrict__ W_hh,
                     const float* __restrict__ b_ih,
                     const float* __restrict__ b_hh,
                     const float* __restrict__ W_lin,
                     const float* __restrict__ b_lin,
                     const float* __restrict__ h0,
                     const float* __restrict__ c0,
                     float* __restrict__ out,
                     int T) {
    __shared__ __align__(16) float hs[2][HD];
    __shared__ float red[4];
    __shared__ __align__(8) u64 mbar[2];

    const int r = threadIdx.x;
    uint32_t rank;
    asm("mov.u32 %0, %%cluster_ctarank;" : "=r"(rank));
    const int q = (int)rank;          // 0..3
    const int gate = r & 3;           // i,f,g,o interleaved within warp
    const int m    = r >> 2;          // local element 0..31
    const int row  = gate * HD + q * QTR + m;
    const int j    = q * QTR + m;     // global h index owned by this group
    const bool prod = (gate == 0);

    // unified activation: act = out_sc * sigm(in_sc*x) + out_b
    const float in_sc  = (gate == 2) ? 2.f : 1.f;
    const float out_sc = (gate == 2) ? 2.f : 1.f;
    const float out_b  = (gate == 2) ? -1.f : 0.f;

    const uint32_t mb0 = smem_u32(&mbar[0]);
    const uint32_t mb1 = smem_u32(&mbar[1]);
    const uint32_t hs_base = smem_u32(&hs[0][0]);

    // peer addresses (3 peers)
    uint32_t p_mb0[3], p_mb1[3], p_hs[3];
    #pragma unroll
    for (int i = 0; i < 3; ++i) {
        uint32_t pr = (uint32_t)((q + 1 + i) & 3);
        p_mb0[i] = mapa_u32(mb0, pr);
        p_mb1[i] = mapa_u32(mb1, pr);
        p_hs[i]  = mapa_u32(hs_base, pr);
    }

    if (r == 0) { mbar_init(mb0, 1); mbar_init(mb1, 1); }

    if (r < HD) hs[0][r] = h0[r];
    float c = prod ? c0[j] : 0.f;

    const float wih  = W_ih[row];
    const float bsum = b_ih[row] + b_hh[row];
    u64 w[64];                         // full row, quarter p at w[16p..16p+16)
    {
        const u64* wrow = (const u64*)(W_hh + (size_t)row * HD);
        #pragma unroll
        for (int k = 0; k < 64; ++k) w[k] = wrow[k];
    }
    __syncthreads();
    if (r == 0) {
        mbar_arrive(mb0);                 // step 0 passes trivially (h0 local)
        mbar_arrive_expect_tx(mb1, TXB);  // arm for step 1's incoming quarters
    }
    __syncthreads();
    cluster_sync();                       // all barriers init/armed before st.async

    float xt = __ldg(&x[0]);

    for (int t = 0; t < T; ++t) {
        const int b  = t & 1;
        const int nb = b ^ 1;
        const uint32_t mbw = b ? mb1 : mb0;
        const uint32_t parity = (uint32_t)((t >> 1) & 1);

        const float xnext = __ldg(&x[(t + 1 < T) ? (t + 1) : t]);

        u64 a0 = pack2(fmaf(wih, xt, bsum), 0.f);
        u64 a1 = 0ull, a2 = 0ull, a3 = 0ull;

        const ulonglong2* hv2 = (const ulonglong2*)(&hs[b][0]);  // 16 chunks/qtr? 8

        // local quarter first (independent of peers): chunks [8q, 8q+8)
        {
            const int p8 = q * 8, p16 = q * 16;
            #pragma unroll
            for (int k = 0; k < 8; k += 2) {
                ulonglong2 u = hv2[p8 + k];
                ulonglong2 v = hv2[p8 + k + 1];
                a0 = ffma2(w[p16 + 2 * k + 0], u.x, a0);
                a1 = ffma2(w[p16 + 2 * k + 1], u.y, a1);
                a2 = ffma2(w[p16 + 2 * k + 2], v.x, a2);
                a3 = ffma2(w[p16 + 2 * k + 3], v.y, a3);
            }
        }

        mbar_wait(mbw, parity);                       // 3 peer quarters landed
        if (r == 0) mbar_arrive_expect_tx(mbw, TXB);  // re-arm for step t+2

        // remaining 3 quarters
        #pragma unroll
        for (int i = 1; i < 4; ++i) {
            const int p = (q + i) & 3;
            const int p8 = p * 8, p16 = p * 16;
            #pragma unroll
            for (int k = 0; k < 8; k += 2) {
                ulonglong2 u = hv2[p8 + k];
                ulonglong2 v = hv2[p8 + k + 1];
                a0 = ffma2(w[p16 + 2 * k + 0], u.x, a0);
                a1 = ffma2(w[p16 + 2 * k + 1], u.y, a1);
                a2 = ffma2(w[p16 + 2 * k + 2], v.x, a2);
                a3 = ffma2(w[p16 + 2 * k + 3], v.y, a3);
            }
        }

        float s0, s1, s2, s3, s4, s5, s6, s7;
        unpack2(a0, s0, s1);
        unpack2(a1, s2, s3);
        unpack2(a2, s4, s5);
        unpack2(a3, s6, s7);
        const float gpre = ((s0 + s1) + (s2 + s3)) + ((s4 + s5) + (s6 + s7));

        const float act = fmaf(out_sc, sigm(in_sc * gpre), out_b);

        const float fv = __shfl_xor_sync(0xFFFFFFFFu, act, 1);
        const float gv = __shfl_xor_sync(0xFFFFFFFFu, act, 2);
        const float ov = __shfl_xor_sync(0xFFFFFFFFu, act, 3);

        if (prod) {
            c = fmaf(fv, c, act * gv);       // act == i on producer lane
            const float hnew = ov * tanh_(c);
            const uint32_t off = (uint32_t)((nb * HD + j) * 4);
            const uint32_t pmb_off = (uint32_t)(nb * 8);  // mbar[nb] offset
            // fire remote stores first (flight starts ASAP)
            st_async_f32(p_hs[0] + off, hnew, (nb ? p_mb1[0] : p_mb0[0]));
            st_async_f32(p_hs[1] + off, hnew, (nb ? p_mb1[1] : p_mb0[1]));
            st_async_f32(p_hs[2] + off, hnew, (nb ? p_mb1[2] : p_mb0[2]));
            hs[nb][j] = hnew;
            (void)pmb_off;
        }
        __syncthreads();
        xt = xnext;
    }

    // CTA0 consumes final h
    if (q == 0) {
        const uint32_t mbw = (T & 1) ? mb1 : mb0;
        mbar_wait(mbw, (uint32_t)((T >> 1) & 1));
        const int bf = T & 1;
        float v = hs[bf][r] * W_lin[r];     // r in [0,128)
        #pragma unroll
        for (int o = 16; o > 0; o >>= 1)
            v += __shfl_down_sync(0xFFFFFFFFu, v, o);
        if ((r & 31) == 0) red[r >> 5] = v;
        __syncthreads();
        if (r == 0) out[0] = red[0] + red[1] + red[2] + red[3] + b_lin[0];
    }
    cluster_sync();   // peers must outlive CTA0's final consumption
}

extern "C" void kernel_launch(void* const* d_in, const int* in_sizes, int n_in,
                              void* d_out, int out_size) {
    const float* x     = (const float*)d_in[0];
    const float* W_ih  = (const float*)d_in[1];
    const float* W_hh  = (const float*)d_in[2];
    const float* b_ih  = (const float*)d_in[3];
    const float* b_hh  = (const float*)d_in[4];
    const float* W_lin = (const float*)d_in[5];
    const float* b_lin = (const float*)d_in[6];
    const float* h0    = (const float*)d_in[7];
    const float* c0    = (const float*)d_in[8];
    float* out = (float*)d_out;

    const int T = in_sizes[0];

    lstm_cluster4_kernel<<<4, TPC>>>(x, W_ih, W_hh, b_ih, b_hh,
                                     W_lin, b_lin, h0, c0, out, T);
}